// round 3
// baseline (speedup 1.0000x reference)
#include <cuda_runtime.h>
#include <cstdint>

#define B_    4
#define T_    1024
#define DIM_  512
#define POOL_ 64
#define K_    50
#define TK_   4      // tokens per k1 block

// Scratch (device globals: allocation-free per harness rules)
__device__ __align__(16) float g_y[B_ * POOL_ * POOL_];   // y[b][t<64][p]
__device__ int   g_idx[T_ * K_];                          // top-50 indices per t
__device__ __align__(16) float g_z[B_ * POOL_ * DIM_];    // z[b][j][d]

// packed fp32x2 FMA (Blackwell FFMA2 — only reachable via PTX)
#define FMA2(d, a, b) \
    asm("fma.rn.f32x2 %0, %1, %2, %3;" : "=l"(d) : "l"(a), "l"(b), "l"(d))
#define PACK_DUP(dst, w) \
    asm("mov.b64 %0, {%1, %1};" : "=l"(dst) : "f"(w))
#define UNPACK2(lo, hi, v) \
    asm("mov.b64 {%0, %1}, %2;" : "=f"(lo), "=f"(hi) : "l"(v))
#define LDS_V2U64(a0, a1, addr) \
    asm("ld.shared.v2.b64 {%0, %1}, [%2];" : "=l"(a0), "=l"(a1) : "r"(addr))

// ---------------------------------------------------------------------------
// Kernel 1: 4 tokens per block. Linear(512->64)+ReLU+LN for 4 batches ×
// 4 tokens via packed f32x2 FMA, then per-token batch-sum + stable top-50.
// grid = 256, block = 256  (tid = p + 64*c ; c = DIM chunk)
//
// smem pool layout (floats), 48KB static total:
//   [0, 8192)      xs2: x pairs,  idx = (pair*4+b)*1024 + d*2 + tk2
//   [8192, 12288)  part: idx = PART + ((b*4+tk)*4 + c)*64 + p
//   tail reuses [0,..): wsum[8][4]@0, wsq[8][4]@32, sv[4][64]@64
// ---------------------------------------------------------------------------
__global__ __launch_bounds__(256) void k1_reduce_topk(
        const float* __restrict__ x,
        const float* __restrict__ w1,
        const float* __restrict__ b1,
        const float* __restrict__ g1,
        const float* __restrict__ bt1) {
    __shared__ float pool[12288];
    const int t0  = blockIdx.x * TK_;
    const int tid = threadIdx.x;
    const int p   = tid & 63;
    const int c   = tid >> 6;
    const int PART = 8192;

    uint32_t sbase;
    asm("{ .reg .u64 t; cvta.to.shared.u64 t, %1; cvt.u32.u64 %0, t; }"
        : "=r"(sbase) : "l"(pool));

    // ---- load x rows into token-pair-interleaved smem ----
    #pragma unroll
    for (int i = tid; i < B_ * TK_ * (DIM_ / 4); i += 256) {   // 2048 float4s
        int row = i >> 7;            // b*4 + tk
        int j   = i & 127;
        int b   = row >> 2;
        int tk  = row & 3;
        int pair = tk >> 1, tk2 = tk & 1;
        float4 v = reinterpret_cast<const float4*>(
            x + ((size_t)b * T_ + (t0 + tk)) * DIM_)[j];
        float* dst = pool + (pair * 4 + b) * 1024 + (4 * j) * 2 + tk2;
        dst[0] = v.x; dst[2] = v.y; dst[4] = v.z; dst[6] = v.w;
    }
    __syncthreads();

    // ---- main GEMM loop: 128 dims per thread, packed over token pairs ----
    unsigned long long acc[B_][2] = {};
    const float* wbase = w1 + (c * 128) * POOL_ + p;
    const uint32_t dbase = sbase + (uint32_t)(c * 128) * 8u;   // d*8 bytes

    #pragma unroll 4
    for (int d4 = 0; d4 < 32; d4++) {
        const float* wp = wbase + d4 * 4 * POOL_;
        float wa = wp[0];
        float wb = wp[POOL_];
        float wc = wp[2 * POOL_];
        float wd = wp[3 * POOL_];
        unsigned long long wwa, wwb, wwc, wwd;
        PACK_DUP(wwa, wa); PACK_DUP(wwb, wb);
        PACK_DUP(wwc, wc); PACK_DUP(wwd, wd);

        #pragma unroll
        for (int pr = 0; pr < 2; pr++) {
            #pragma unroll
            for (int b = 0; b < B_; b++) {
                uint32_t a0 = dbase + (uint32_t)((pr * 4 + b) * 4096 + d4 * 32);
                unsigned long long v0, v1, v2, v3;
                LDS_V2U64(v0, v1, a0);
                LDS_V2U64(v2, v3, a0 + 16);
                FMA2(acc[b][pr], v0, wwa);
                FMA2(acc[b][pr], v1, wwb);
                FMA2(acc[b][pr], v2, wwc);
                FMA2(acc[b][pr], v3, wwd);
            }
        }
    }

    // ---- spill partials ----
    __syncthreads();   // xs2 reads done everywhere before part overwrites pool use
    #pragma unroll
    for (int b = 0; b < B_; b++) {
        #pragma unroll
        for (int pr = 0; pr < 2; pr++) {
            float lo, hi;
            UNPACK2(lo, hi, acc[b][pr]);
            pool[PART + ((b * 4 + (pr * 2 + 0)) * 4 + c) * 64 + p] = lo;
            pool[PART + ((b * 4 + (pr * 2 + 1)) * 4 + c) * 64 + p] = hi;
        }
    }
    __syncthreads();

    // ---- tail: tid = tk*64 + p ; one (token, pool-idx) per thread ----
    {
        const int tk = tid >> 6;
        const int pp = tid & 63;
        const int t  = t0 + tk;
        const float bias = b1[pp];

        float vv[B_];
        #pragma unroll
        for (int b = 0; b < B_; b++) {
            const float* pb = pool + PART + ((b * 4 + tk) * 4) * 64 + pp;
            vv[b] = fmaxf(pb[0] + pb[64] + pb[128] + pb[192] + bias, 0.f);
        }

        float s[B_], q[B_];
        #pragma unroll
        for (int b = 0; b < B_; b++) { s[b] = vv[b]; q[b] = vv[b] * vv[b]; }
        #pragma unroll
        for (int off = 16; off > 0; off >>= 1) {
            #pragma unroll
            for (int b = 0; b < B_; b++) {
                s[b] += __shfl_xor_sync(0xffffffffu, s[b], off);
                q[b] += __shfl_xor_sync(0xffffffffu, q[b], off);
            }
        }
        const int w = tid >> 5;           // 8 warps
        if ((tid & 31) == 0) {
            #pragma unroll
            for (int b = 0; b < B_; b++) {
                pool[w * 4 + b]      = s[b];   // wsum @ 0
                pool[32 + w * 4 + b] = q[b];   // wsq  @ 32
            }
        }
        __syncthreads();

        const float gp = g1[pp], bp = bt1[pp];
        float ysum = 0.f;
        float yv[B_];
        #pragma unroll
        for (int b = 0; b < B_; b++) {
            float S = pool[(tk * 2) * 4 + b]      + pool[(tk * 2 + 1) * 4 + b];
            float Q = pool[32 + (tk * 2) * 4 + b] + pool[32 + (tk * 2 + 1) * 4 + b];
            float m   = S * (1.f / POOL_);
            float var = Q * (1.f / POOL_) - m * m;
            float r   = rsqrtf(var + 1e-5f);
            yv[b] = (vv[b] - m) * r * gp + bp;
            ysum += yv[b];
        }

        if (t < POOL_) {
            #pragma unroll
            for (int b = 0; b < B_; b++)
                g_y[(b * POOL_ + t) * POOL_ + pp] = yv[b];
        }

        pool[64 + tk * 64 + pp] = ysum;     // sv @ 64
        __syncthreads();

        const float mine = ysum;
        int rank = 0;
        #pragma unroll
        for (int j = 0; j < POOL_; j++) {
            float o = pool[64 + tk * 64 + j];
            rank += (o > mine) || ((o == mine) && (j < pp));
        }
        if (rank < K_) g_idx[t * K_ + rank] = pp;
    }
}

// ---------------------------------------------------------------------------
// Kernel 2: z[b,j,:] = LN(relu(y[b,j,:] @ w2 + b2))   (256 distinct rows)
// grid = B_*POOL_, block = 512
// ---------------------------------------------------------------------------
__global__ void k2_expand(const float* __restrict__ w2,
                          const float* __restrict__ b2,
                          const float* __restrict__ g2,
                          const float* __restrict__ bt2) {
    const int bj = blockIdx.x;
    const int d  = threadIdx.x;

    __shared__ float yr[POOL_];
    if (d < POOL_) yr[d] = g_y[bj * POOL_ + d];
    __syncthreads();

    float acc = b2[d];
    #pragma unroll
    for (int p = 0; p < POOL_; p++)
        acc += yr[p] * w2[p * DIM_ + d];

    float v = fmaxf(acc, 0.f);

    float s = v, q = v * v;
    #pragma unroll
    for (int off = 16; off > 0; off >>= 1) {
        s += __shfl_xor_sync(0xffffffffu, s, off);
        q += __shfl_xor_sync(0xffffffffu, q, off);
    }
    __shared__ float ps[16], pq[16];
    const int w = d >> 5;
    if ((d & 31) == 0) { ps[w] = s; pq[w] = q; }
    __syncthreads();
    float S = 0.f, Q = 0.f;
    #pragma unroll
    for (int i = 0; i < 16; i++) { S += ps[i]; Q += pq[i]; }

    float m   = S * (1.f / DIM_);
    float var = Q * (1.f / DIM_) - m * m;
    g_z[bj * DIM_ + d] = (v - m) * rsqrtf(var + 1e-5f) * g2[d] + bt2[d];
}

// ---------------------------------------------------------------------------
// Kernel 3: out[b,t,k,:] = z[b, idx[t,k], :]  — the 419 MB write stream.
// ---------------------------------------------------------------------------
__global__ void k3_gather(float* __restrict__ out) {
    const int warp = threadIdx.x >> 5;
    const int lane = threadIdx.x & 31;
    const unsigned base = blockIdx.x * 64u;

    #pragma unroll
    for (int i = 0; i < 4; i++) {
        unsigned r   = base + warp + i * 16;
        unsigned b   = r / (unsigned)(T_ * K_);
        unsigned rem = r - b * (unsigned)(T_ * K_);
        unsigned t   = rem / K_;
        unsigned k   = rem - t * K_;
        int j = g_idx[t * K_ + k];

        const float4* src = reinterpret_cast<const float4*>(g_z)
                            + (size_t)(b * POOL_ + j) * (DIM_ / 4);
        float4* dst = reinterpret_cast<float4*>(out)
                      + (size_t)r * (DIM_ / 4);
        #pragma unroll
        for (int cc = 0; cc < 4; cc++) {
            float4 v = __ldg(src + lane + 32 * cc);
            __stcs(dst + lane + 32 * cc, v);
        }
    }
}

// ---------------------------------------------------------------------------
extern "C" void kernel_launch(void* const* d_in, const int* in_sizes, int n_in,
                              void* d_out, int out_size) {
    const float* x   = (const float*)d_in[0];
    const float* w1  = (const float*)d_in[1];
    const float* b1  = (const float*)d_in[2];
    const float* g1  = (const float*)d_in[3];
    const float* bt1 = (const float*)d_in[4];
    const float* w2  = (const float*)d_in[5];
    const float* b2  = (const float*)d_in[6];
    const float* g2  = (const float*)d_in[7];
    const float* bt2 = (const float*)d_in[8];
    float* out = (float*)d_out;

    k1_reduce_topk<<<T_ / TK_, 256>>>(x, w1, b1, g1, bt1);
    k2_expand<<<B_ * POOL_, DIM_>>>(w2, b2, g2, bt2);
    k3_gather<<<(B_ * T_ * K_) / 64, 512>>>(out);
}